// round 16
// baseline (speedup 1.0000x reference)
#include <cuda_runtime.h>
#include <cuda_fp16.h>
#include <math.h>
#include <stdint.h>

#define BB 128
#define NN 256
#define DD 512
#define OO 512
#define MROWS (BB * NN)   // 32768

// ---------------------------------------------------------------------------
// Scratch (no cudaMalloc allowed)
// ---------------------------------------------------------------------------
__device__ __half g_x16[(size_t)MROWS * DD];   // compact: fp16(Obs) then fp16(h1+h2)
__device__ __half g_h1[(size_t)MROWS * OO];    // compact fp16 GEMM1 output
__device__ float  g_o3[(size_t)MROWS * OO];    // compact fp32 GEMM3 output
__device__ __half g_wg[3 * (size_t)DD * OO];   // (g∘W)^T per layer: [N][K] fp16
__device__ float  g_mean[MROWS];
__device__ float  g_rstd[MROWS];
__device__ float  g_Sp[3 * 8 * OO];
__device__ float  g_Tp[3 * 8 * OO];
__device__ float  g_ps1[(size_t)MROWS * 8];
__device__ float  g_pq1[(size_t)MROWS * 8];
__device__ float  g_ps2[(size_t)MROWS * 8];
__device__ float  g_pq2[(size_t)MROWS * 8];
__device__ int    g_cnt[BB];
__device__ int    g_ntot[2];                   // [0]=total valid, [1]=padded to 128
__device__ int    g_fwd[MROWS];                // compact -> orig row
__device__ int    g_inv[MROWS];                // orig -> compact row (-1 invalid)

// ---------------------------------------------------------------------------
// Helpers (sm_80-era PTX only — must assemble under compute_103)
// ---------------------------------------------------------------------------
__device__ __forceinline__ uint32_t smem_to_u32(const void* p) {
    uint32_t a;
    asm("{ .reg .u64 t; cvta.to.shared.u64 t, %1; cvt.u32.u64 %0, t; }"
        : "=r"(a) : "l"(p));
    return a;
}
__device__ __forceinline__ void cp16(uint32_t dst, const void* src) {
    asm volatile("cp.async.cg.shared.global [%0], [%1], 16;"
                 :: "r"(dst), "l"(src) : "memory");
}
__device__ __forceinline__ void ldm_x4(uint32_t* r, uint32_t addr) {
    asm volatile("ldmatrix.sync.aligned.m8n8.x4.shared.b16 {%0,%1,%2,%3}, [%4];"
                 : "=r"(r[0]), "=r"(r[1]), "=r"(r[2]), "=r"(r[3]) : "r"(addr));
}
__device__ __forceinline__ void mma_fp16(float* c, const uint32_t* a,
                                         uint32_t b0, uint32_t b1) {
    asm volatile(
        "mma.sync.aligned.m16n8k16.row.col.f32.f16.f16.f32 "
        "{%0,%1,%2,%3}, {%4,%5,%6,%7}, {%8,%9}, {%0,%1,%2,%3};"
        : "+f"(c[0]), "+f"(c[1]), "+f"(c[2]), "+f"(c[3])
        : "r"(a[0]), "r"(a[1]), "r"(a[2]), "r"(a[3]), "r"(b0), "r"(b1));
}

// ---------------------------------------------------------------------------
// Compaction A: per-b valid counts (grant-at-least-one). grid BB x 256.
// ---------------------------------------------------------------------------
__global__ void maskcnt_kernel(const unsigned* __restrict__ mask,
                               int* __restrict__ cnt) {
    const int b = blockIdx.x, n = threadIdx.x;
    const int raw = mask[(size_t)b * NN + n] != 0u;
    const int any = __syncthreads_or(raw);
    const int v = raw | ((!any) & (n == 0));
    const unsigned bal = __ballot_sync(0xFFFFFFFFu, v);
    __shared__ int wc[8];
    if ((n & 31) == 0) wc[n >> 5] = __popc(bal);
    __syncthreads();
    if (n == 0) {
        int s = 0;
        #pragma unroll
        for (int i = 0; i < 8; i++) s += wc[i];
        cnt[b] = s;
    }
}

// ---------------------------------------------------------------------------
// Compaction B: write fwd/inv maps + ntot (scan of counts done in-block).
// grid BB x 256.
// ---------------------------------------------------------------------------
__global__ void cwrite_kernel(const unsigned* __restrict__ mask,
                              const int* __restrict__ cnt,
                              int* __restrict__ fwd, int* __restrict__ inv,
                              int* __restrict__ ntot) {
    const int b = blockIdx.x, n = threadIdx.x;
    __shared__ int scnt[BB];
    __shared__ int s_off;
    __shared__ int wc[8];

    if (n < BB) scnt[n] = cnt[n];

    const int raw = mask[(size_t)b * NN + n] != 0u;
    const int any = __syncthreads_or(raw);   // barrier: scnt loads done
    const int v = raw | ((!any) & (n == 0));
    const unsigned bal = __ballot_sync(0xFFFFFFFFu, v);
    if ((n & 31) == 0) wc[n >> 5] = __popc(bal);
    if (n == 0) {
        int o = 0, tot = 0;
        #pragma unroll 4
        for (int i = 0; i < BB; i++) {
            if (i < b) o += scnt[i];
            tot += scnt[i];
        }
        s_off = o;
        if (b == 0) {
            ntot[0] = tot;
            ntot[1] = (tot + 127) & ~127;
        }
    }
    __syncthreads();

    int wbase = 0;
    for (int i = 0; i < (n >> 5); i++) wbase += wc[i];
    const int rank = s_off + wbase + __popc(bal & ((1u << (n & 31)) - 1u));
    if (v) {
        fwd[rank] = b * NN + n;
        inv[b * NN + n] = rank;
    } else {
        inv[b * NN + n] = -1;
    }
}

// ---------------------------------------------------------------------------
// Fused prep, 128 threads/block. Blocks [0, 24): weight prep (layer l,
// k-slab of 64). Blocks [24, 24+MROWS): one compact row each — gather via
// fwd, fp16 convert, mean/rstd. Early exit past padded count.
// ---------------------------------------------------------------------------
__global__ __launch_bounds__(128)
void prep_kernel(const float* __restrict__ Obs,
                 const int* __restrict__ fwd, const int* __restrict__ ntot,
                 __half* __restrict__ x16,
                 float* __restrict__ mean, float* __restrict__ rstd,
                 const float* __restrict__ W1, const float* __restrict__ W2,
                 const float* __restrict__ W3,
                 const float* __restrict__ g1, const float* __restrict__ g2,
                 const float* __restrict__ g3,
                 const float* __restrict__ b1, const float* __restrict__ b2,
                 const float* __restrict__ b3,
                 __half* __restrict__ wg,
                 float* __restrict__ Sp, float* __restrict__ Tp) {
    const int bid = blockIdx.x;
    const int tid = threadIdx.x;

    if (bid < 24) {
        // ---- weight prep: layer l, k-slab [k0, k0+64) ----
        const int l = bid >> 3;
        const int slab = bid & 7;
        const float* W = (l == 0) ? W1 : (l == 1) ? W2 : W3;
        const float* g = (l == 0) ? g1 : (l == 1) ? g2 : g3;
        const float* b = (l == 0) ? b1 : (l == 1) ? b2 : b3;
        __half* wgo = wg + (size_t)l * DD * OO;
        const int k0 = slab * 64;

        __shared__ float sg[64], sb[64];
        if (tid < 64)       sg[tid] = g[k0 + tid];
        else                sb[tid - 64] = b[k0 + tid - 64];
        __syncthreads();

        #pragma unroll
        for (int half = 0; half < 4; half++) {
            const int n = tid + half * 128;
            float s = 0.f, t = 0.f;
            #pragma unroll
            for (int i8 = 0; i8 < 8; i8++) {
                __align__(16) __half h[8];
                #pragma unroll
                for (int j = 0; j < 8; j++) {
                    const int kk = i8 * 8 + j;
                    const float w = W[(size_t)(k0 + kk) * OO + n];
                    const float gw = sg[kk] * w;
                    s += gw;
                    t += sb[kk] * w;
                    h[j] = __float2half_rn(gw);
                }
                *reinterpret_cast<uint4*>(wgo + (size_t)n * DD + k0 + i8 * 8) =
                    *reinterpret_cast<const uint4*>(h);
            }
            Sp[(size_t)(l * 8 + slab) * OO + n] = s;
            Tp[(size_t)(l * 8 + slab) * OO + n] = t;
        }
    } else {
        const int row = bid - 24;
        if (row >= __ldg(&ntot[1])) return;
        const int total = __ldg(&ntot[0]);

        float4 v = make_float4(0.f, 0.f, 0.f, 0.f);
        if (row < total) {
            const int orig = __ldg(&fwd[row]);
            v = reinterpret_cast<const float4*>(Obs + (size_t)orig * DD)[tid];
        }
        __half2* p = reinterpret_cast<__half2*>(x16 + (size_t)row * DD);
        p[tid * 2]     = __halves2half2(__float2half_rn(v.x), __float2half_rn(v.y));
        p[tid * 2 + 1] = __halves2half2(__float2half_rn(v.z), __float2half_rn(v.w));

        float s  = v.x + v.y + v.z + v.w;
        float ss = v.x * v.x + v.y * v.y + v.z * v.z + v.w * v.w;
        #pragma unroll
        for (int o = 16; o > 0; o >>= 1) {
            s  += __shfl_xor_sync(0xFFFFFFFFu, s,  o);
            ss += __shfl_xor_sync(0xFFFFFFFFu, ss, o);
        }
        __shared__ float sh_s[4], sh_ss[4];
        const int w = tid >> 5;
        if ((tid & 31) == 0) { sh_s[w] = s; sh_ss[w] = ss; }
        __syncthreads();
        if (tid == 0) {
            s  = sh_s[0] + sh_s[1] + sh_s[2] + sh_s[3];
            ss = sh_ss[0] + sh_ss[1] + sh_ss[2] + sh_ss[3];
            const float mn  = s * (1.0f / DD);
            const float var = ss * (1.0f / DD) - mn * mn;
            mean[row] = mn;
            rstd[row] = rsqrtf(var + 1e-5f);
        }
    }
}

// ---------------------------------------------------------------------------
// fp16 HMMA GEMM (compact rows) with fused LN affine epilogue.
// Prologue (hidden under mainloop): reduce per-column S/T from 8 slab
// partials; PSTATS: reduce per-row mean/rstd from 8 chunk partials.
// Blocks with m0 >= padded row count exit immediately.
// ---------------------------------------------------------------------------
template <bool TANH, bool STATS, bool RESID, bool PSTATS, typename OutT>
__global__ __launch_bounds__(256, 2)
void gemm_ln_kernel(const __half* __restrict__ A,
                    const __half* __restrict__ B,
                    const float* __restrict__ mean,
                    const float* __restrict__ rstd,
                    const float* __restrict__ psin,
                    const float* __restrict__ pqin,
                    const float* __restrict__ SpL,
                    const float* __restrict__ TpL,
                    const __half* __restrict__ resid,
                    float* __restrict__ ps,
                    float* __restrict__ pq,
                    OutT* __restrict__ C,
                    const int* __restrict__ ntot) {
    if ((int)(blockIdx.y * 128) >= __ldg(&ntot[1])) return;

    extern __shared__ char smem[];
    const uint32_t sb = smem_to_u32(smem);
    __shared__ float s_mn[128], s_rs[128];
    __shared__ float s_S[128], s_T[128];

    const int tid  = threadIdx.x;
    const int lane = tid & 31;
    const int wid  = tid >> 5;
    const int m0 = blockIdx.y * 128;
    const int n0 = blockIdx.x * 128;
    const int warp_m = (wid >> 1) * 32;
    const int warp_n = (wid & 1) * 64;

    // Prologues: latency hidden under the mainloop (ordered by its barriers)
    if (tid < 128) {
        float s = 0.f, t = 0.f;
        #pragma unroll
        for (int i = 0; i < 8; i++) {
            s += SpL[(size_t)i * OO + n0 + tid];
            t += TpL[(size_t)i * OO + n0 + tid];
        }
        s_S[tid] = s;
        s_T[tid] = t;
    } else if (PSTATS && tid < 256) {
        const int r = tid - 128;
        float s = 0.f, q = 0.f;
        #pragma unroll
        for (int i = 0; i < 8; i++) {
            s += psin[(size_t)(m0 + r) * 8 + i];
            q += pqin[(size_t)(m0 + r) * 8 + i];
        }
        const float mn  = s * (1.0f / DD);
        const float var = q * (1.0f / DD) - mn * mn;
        s_mn[r] = mn;
        s_rs[r] = rsqrtf(var + 1e-5f);
    }

    float acc[2][8][4];
    #pragma unroll
    for (int i = 0; i < 2; i++)
        #pragma unroll
        for (int j = 0; j < 8; j++)
            #pragma unroll
            for (int q = 0; q < 4; q++) acc[i][j][q] = 0.0f;

    const int arow  = warp_m + (lane & 7) + ((lane >> 3) & 1) * 8;
    const int akblk = (lane >> 4) & 1;
    const int ax    = arow & 3;
    const int brow  = warp_n + (lane & 7) + ((lane >> 4) & 1) * 8;
    const int bkblk = (lane >> 3) & 1;
    const int bx    = brow & 3;

    #define AOFF(mt, kb) \
        (uint32_t)((arow + (mt) * 16) * 64 + (((((kb) >> 3) + akblk) ^ ax) & 3) * 16)
    #define BOFF(jj, kb) \
        (uint32_t)((brow + (jj) * 16) * 64 + (((((kb) >> 3) + bkblk) ^ bx) & 3) * 16)

    const int c0row = tid >> 2,          c0ch = tid & 3;
    const int c1row = (tid + 256) >> 2;
    const uint32_t d0 = (uint32_t)(c0row * 64 + ((c0ch ^ (c0row & 3)) << 4));
    const uint32_t d1 = (uint32_t)(c1row * 64 + ((c0ch ^ (c1row & 3)) << 4));
    const size_t gA0 = (size_t)(m0 + c0row) * DD + c0ch * 8;
    const size_t gA1 = (size_t)(m0 + c1row) * DD + c0ch * 8;
    const size_t gB0 = (size_t)(n0 + c0row) * DD + c0ch * 8;
    const size_t gB1 = (size_t)(n0 + c1row) * DD + c0ch * 8;

    #define LOAD_STAGE(it, st) do {                                      \
        const int _k0 = (it) * 32;                                       \
        const uint32_t _sa = sb + (uint32_t)(st) * 16384u;               \
        const uint32_t _sbb = _sa + 8192u;                               \
        cp16(_sa + d0, A + gA0 + _k0);                                   \
        cp16(_sa + d1, A + gA1 + _k0);                                   \
        cp16(_sbb + d0, B + gB0 + _k0);                                  \
        cp16(_sbb + d1, B + gB1 + _k0);                                  \
        asm volatile("cp.async.commit_group;" ::: "memory");             \
    } while (0)

    LOAD_STAGE(0, 0);
    LOAD_STAGE(1, 1);

    const int NK = DD / 32;   // 16
    int st = 0;
    for (int it = 0; it < NK; it++) {
        if (it + 1 < NK) {
            asm volatile("cp.async.wait_group 1;" ::: "memory");
        } else {
            asm volatile("cp.async.wait_group 0;" ::: "memory");
        }
        __syncthreads();

        if (it + 2 < NK) {
            int st2 = st + 2; if (st2 >= 3) st2 -= 3;
            LOAD_STAGE(it + 2, st2);
        }

        const uint32_t sa  = sb + (uint32_t)st * 16384u;
        const uint32_t sbB = sa + 8192u;
        #pragma unroll
        for (int ks = 0; ks < 2; ks++) {
            const int kb = ks * 16;
            uint32_t af[2][4];
            #pragma unroll
            for (int mt = 0; mt < 2; mt++)
                ldm_x4(af[mt], sa + AOFF(mt, kb));
            uint32_t bf[4][4];
            #pragma unroll
            for (int jj = 0; jj < 4; jj++)
                ldm_x4(bf[jj], sbB + BOFF(jj, kb));
            #pragma unroll
            for (int j = 0; j < 8; j++) {
                const int jj = j >> 1, jh = (j & 1) * 2;
                const uint32_t b0 = bf[jj][jh], b1 = bf[jj][jh + 1];
                #pragma unroll
                for (int mt = 0; mt < 2; mt++)
                    mma_fp16(acc[mt][j], af[mt], b0, b1);
            }
        }
        if (++st >= 3) st = 0;
    }
    #undef LOAD_STAGE
    #undef AOFF
    #undef BOFF

    // Epilogue: fused LN affine (+tanh) (+residual) (+stats partials)
    #pragma unroll
    for (int mt = 0; mt < 2; mt++) {
        const int lr0 = warp_m + mt * 16 + (lane >> 2);
        const int lr1 = lr0 + 8;
        const int r0 = m0 + lr0, r1 = m0 + lr1;
        const float mn0 = PSTATS ? s_mn[lr0] : mean[r0];
        const float rs0 = PSTATS ? s_rs[lr0] : rstd[r0];
        const float mn1 = PSTATS ? s_mn[lr1] : mean[r1];
        const float rs1 = PSTATS ? s_rs[lr1] : rstd[r1];
        float s0 = 0.f, q0 = 0.f, s1 = 0.f, q1 = 0.f;
        #pragma unroll
        for (int j = 0; j < 8; j++) {
            const int cl = warp_n + j * 8 + (lane & 3) * 2;   // local column
            const int col = n0 + cl;
            const float sc0 = s_S[cl], sc1 = s_S[cl + 1];
            const float tc0 = s_T[cl], tc1 = s_T[cl + 1];
            float v0 = rs0 * (acc[mt][j][0] - mn0 * sc0) + tc0;
            float v1 = rs0 * (acc[mt][j][1] - mn0 * sc1) + tc1;
            float v2 = rs1 * (acc[mt][j][2] - mn1 * sc0) + tc0;
            float v3 = rs1 * (acc[mt][j][3] - mn1 * sc1) + tc1;
            if (TANH) { v0 = tanhf(v0); v1 = tanhf(v1); v2 = tanhf(v2); v3 = tanhf(v3); }
            if (RESID) {
                const __half2 h2a = *reinterpret_cast<const __half2*>(
                    resid + (size_t)r0 * OO + col);
                const __half2 h2b = *reinterpret_cast<const __half2*>(
                    resid + (size_t)r1 * OO + col);
                v0 += __half2float(__low2half(h2a));
                v1 += __half2float(__high2half(h2a));
                v2 += __half2float(__low2half(h2b));
                v3 += __half2float(__high2half(h2b));
            }
            if (sizeof(OutT) == 2) {
                const __half h0 = __float2half_rn(v0), h1 = __float2half_rn(v1);
                const __half h2 = __float2half_rn(v2), h3 = __float2half_rn(v3);
                *reinterpret_cast<__half2*>((__half*)C + (size_t)r0 * OO + col) =
                    __halves2half2(h0, h1);
                *reinterpret_cast<__half2*>((__half*)C + (size_t)r1 * OO + col) =
                    __halves2half2(h2, h3);
                if (STATS) {
                    const float f0 = __half2float(h0), f1 = __half2float(h1);
                    const float f2 = __half2float(h2), f3 = __half2float(h3);
                    s0 += f0 + f1; q0 += f0 * f0 + f1 * f1;
                    s1 += f2 + f3; q1 += f2 * f2 + f3 * f3;
                }
            } else {
                *reinterpret_cast<float2*>((float*)C + (size_t)r0 * OO + col) =
                    make_float2(v0, v1);
                *reinterpret_cast<float2*>((float*)C + (size_t)r1 * OO + col) =
                    make_float2(v2, v3);
            }
        }
        if (STATS) {
            #pragma unroll
            for (int o = 1; o <= 2; o <<= 1) {
                s0 += __shfl_xor_sync(0xFFFFFFFFu, s0, o);
                q0 += __shfl_xor_sync(0xFFFFFFFFu, q0, o);
                s1 += __shfl_xor_sync(0xFFFFFFFFu, s1, o);
                q1 += __shfl_xor_sync(0xFFFFFFFFu, q1, o);
            }
            if ((lane & 3) == 0) {
                const int chunk = blockIdx.x * 2 + (wid & 1);
                ps[(size_t)r0 * 8 + chunk] = s0;
                pq[(size_t)r0 * 8 + chunk] = q0;
                ps[(size_t)r1 * 8 + chunk] = s1;
                pq[(size_t)r1 * 8 + chunk] = q1;
            }
        }
    }
}

// ---------------------------------------------------------------------------
// Masked softmax over axis=1 with compact-row gather.
// grid (BB, 8), 256 threads; 256n x 64o panel staged in 64KB dynamic SMEM.
// ---------------------------------------------------------------------------
__global__ __launch_bounds__(256)
void softmax_kernel(float* __restrict__ out,
                    const float* __restrict__ o3c,
                    const int* __restrict__ inv) {
    extern __shared__ float sv[];   // [256][64]
    __shared__ int sidx[NN];
    __shared__ float red_m[4][64], red_s[4][64];

    const int b  = blockIdx.x;
    const int o0 = blockIdx.y * 64;
    const int tid = threadIdx.x;

    sidx[tid] = inv[b * NN + tid];
    __syncthreads();

    for (int idx = tid; idx < NN * 64; idx += 256) {
        const int n = idx >> 6, c = idx & 63;
        const int ci = sidx[n];
        sv[idx] = (ci >= 0) ? o3c[(size_t)ci * OO + o0 + c] : 0.0f;
    }
    __syncthreads();

    const int col = tid & 63;
    const int seg = tid >> 6;
    float m = -INFINITY, s = 0.0f;
    for (int n = seg * 64; n < seg * 64 + 64; n++) {
        if (sidx[n] >= 0) {
            const float v = sv[n * 64 + col];
            const float nm = fmaxf(m, v);
            s = s * __expf(m - nm) + __expf(v - nm);
            m = nm;
        }
    }
    red_m[seg][col] = m;
    red_s[seg][col] = s;
    __syncthreads();

    if (seg == 0) {
        float M = red_m[0][col];
        #pragma unroll
        for (int i = 1; i < 4; i++) M = fmaxf(M, red_m[i][col]);
        float SS = 0.0f;
        #pragma unroll
        for (int i = 0; i < 4; i++) {
            const float mi = red_m[i][col];
            if (mi != -INFINITY) SS += red_s[i][col] * __expf(mi - M);
        }
        red_m[0][col] = M;
        red_s[0][col] = 1.0f / SS;
    }
    __syncthreads();

    const float M  = red_m[0][col];
    const float rs = red_s[0][col];
    float* base = out + (size_t)b * NN * OO + o0;
    for (int n = seg * 64; n < seg * 64 + 64; n++) {
        const float v = (sidx[n] >= 0) ? __expf(sv[n * 64 + col] - M) * rs : 0.0f;
        base[(size_t)n * OO + col] = v;
    }
}

// ---------------------------------------------------------------------------
// Launch
// ---------------------------------------------------------------------------
extern "C" void kernel_launch(void* const* d_in, const int* in_sizes, int n_in,
                              void* d_out, int out_size) {
    const float*    Obs  = (const float*)d_in[0];
    const unsigned* mask = (const unsigned*)d_in[1];
    const float* g1 = (const float*)d_in[2];
    const float* b1 = (const float*)d_in[3];
    const float* W1 = (const float*)d_in[4];
    const float* g2 = (const float*)d_in[5];
    const float* b2 = (const float*)d_in[6];
    const float* W2 = (const float*)d_in[7];
    const float* g3 = (const float*)d_in[8];
    const float* b3 = (const float*)d_in[9];
    const float* W3 = (const float*)d_in[10];
    float* out = (float*)d_out;

    __half *x16, *h1, *wg;
    float *o3, *mean, *rstd, *Sp, *Tp, *ps1, *pq1, *ps2, *pq2;
    int *cnt, *ntot, *fwd, *inv;
    cudaGetSymbolAddress((void**)&x16, g_x16);
    cudaGetSymbolAddress((void**)&h1, g_h1);
    cudaGetSymbolAddress((void**)&o3, g_o3);
    cudaGetSymbolAddress((void**)&wg, g_wg);
    cudaGetSymbolAddress((void**)&mean, g_mean);
    cudaGetSymbolAddress((void**)&rstd, g_rstd);
    cudaGetSymbolAddress((void**)&Sp, g_Sp);
    cudaGetSymbolAddress((void**)&Tp, g_Tp);
    cudaGetSymbolAddress((void**)&ps1, g_ps1);
    cudaGetSymbolAddress((void**)&pq1, g_pq1);
    cudaGetSymbolAddress((void**)&ps2, g_ps2);
    cudaGetSymbolAddress((void**)&pq2, g_pq2);
    cudaGetSymbolAddress((void**)&cnt, g_cnt);
    cudaGetSymbolAddress((void**)&ntot, g_ntot);
    cudaGetSymbolAddress((void**)&fwd, g_fwd);
    cudaGetSymbolAddress((void**)&inv, g_inv);

    static bool attr_done = false;
    const int DSMEM = 49152;            // 3 stages x 16KB
    const int SMEM_SOFT = NN * 64 * 4;  // 64KB
    if (!attr_done) {
        cudaFuncSetAttribute(
            (const void*)gemm_ln_kernel<true, true, false, false, __half>,
            cudaFuncAttributeMaxDynamicSharedMemorySize, DSMEM);
        cudaFuncSetAttribute(
            (const void*)gemm_ln_kernel<true, true, true, true, __half>,
            cudaFuncAttributeMaxDynamicSharedMemorySize, DSMEM);
        cudaFuncSetAttribute(
            (const void*)gemm_ln_kernel<false, false, false, true, float>,
            cudaFuncAttributeMaxDynamicSharedMemorySize, DSMEM);
        cudaFuncSetAttribute((const void*)softmax_kernel,
                             cudaFuncAttributeMaxDynamicSharedMemorySize, SMEM_SOFT);
        attr_done = true;
    }

    const dim3 gGemm(OO / 128, MROWS / 128);   // (4, 256); tail blocks exit

    // Compaction (2 launches)
    maskcnt_kernel<<<BB, 256>>>(mask, cnt);
    cwrite_kernel<<<BB, 256>>>(mask, cnt, fwd, inv, ntot);

    // Fused prep: weight prep (24 blocks first) + gather-stats rows
    prep_kernel<<<24 + MROWS, 128>>>(Obs, fwd, ntot, x16, mean, rstd,
                                     W1, W2, W3, g1, g2, g3, b1, b2, b3,
                                     wg, Sp, Tp);

    // Block 1: GEMM1 -> h1 (fp16 compact) + stats partials of h1
    gemm_ln_kernel<true, true, false, false, __half><<<gGemm, 256, DSMEM>>>(
        x16, wg, mean, rstd, nullptr, nullptr, Sp, Tp, nullptr,
        ps1, pq1, h1, ntot);

    // Block 2: GEMM2 -> x16 = fp16(h1 + tanh(...)) + stats partials
    gemm_ln_kernel<true, true, true, true, __half><<<gGemm, 256, DSMEM>>>(
        h1, wg + (size_t)DD * OO, nullptr, nullptr, ps1, pq1,
        Sp + 8 * OO, Tp + 8 * OO, h1, ps2, pq2, x16, ntot);

    // Block 3: GEMM3 -> o3 (fp32 compact)
    gemm_ln_kernel<false, false, false, true, float><<<gGemm, 256, DSMEM>>>(
        x16, wg + 2 * (size_t)DD * OO, nullptr, nullptr, ps2, pq2,
        Sp + 16 * OO, Tp + 16 * OO, nullptr, nullptr, nullptr, o3, ntot);

    // Masked softmax over axis=1: gather compact rows, write dense output
    softmax_kernel<<<dim3(BB, 8), 256, SMEM_SOFT>>>(out, o3, inv);
}

// round 17
// speedup vs baseline: 1.2706x; 1.2706x over previous
#include <cuda_runtime.h>
#include <cuda_fp16.h>
#include <math.h>
#include <stdint.h>

#define BB 128
#define NN 256
#define DD 512
#define OO 512
#define MROWS (BB * NN)   // 32768

// ---------------------------------------------------------------------------
// Scratch (no cudaMalloc allowed)
// ---------------------------------------------------------------------------
__device__ __half g_x16[(size_t)MROWS * DD];   // compact: fp16(Obs) then fp16(h1+h2)
__device__ __half g_h1[(size_t)MROWS * OO];    // compact fp16 GEMM1 output
__device__ float  g_o3[(size_t)MROWS * OO];    // compact fp32 GEMM3 output
__device__ __half g_wg[3 * (size_t)DD * OO];   // (g∘W)^T per layer: [N][K] fp16
__device__ float  g_mean[MROWS];
__device__ float  g_rstd[MROWS];
__device__ float  g_Sp[3 * 8 * OO];
__device__ float  g_Tp[3 * 8 * OO];
__device__ float  g_ps1[(size_t)MROWS * 8];
__device__ float  g_pq1[(size_t)MROWS * 8];
__device__ float  g_ps2[(size_t)MROWS * 8];
__device__ float  g_pq2[(size_t)MROWS * 8];
__device__ int    g_cnt[BB];
__device__ int    g_ntot[2];                   // [0]=total valid, [1]=padded to 128
__device__ int    g_fwd[MROWS];                // compact -> orig row
__device__ int    g_inv[MROWS];                // orig -> compact row (-1 invalid)

// ---------------------------------------------------------------------------
// Helpers (sm_80-era PTX only — must assemble under compute_103)
// ---------------------------------------------------------------------------
__device__ __forceinline__ uint32_t smem_to_u32(const void* p) {
    uint32_t a;
    asm("{ .reg .u64 t; cvta.to.shared.u64 t, %1; cvt.u32.u64 %0, t; }"
        : "=r"(a) : "l"(p));
    return a;
}
__device__ __forceinline__ void cp16(uint32_t dst, const void* src) {
    asm volatile("cp.async.cg.shared.global [%0], [%1], 16;"
                 :: "r"(dst), "l"(src) : "memory");
}
__device__ __forceinline__ void ldm_x4(uint32_t* r, uint32_t addr) {
    asm volatile("ldmatrix.sync.aligned.m8n8.x4.shared.b16 {%0,%1,%2,%3}, [%4];"
                 : "=r"(r[0]), "=r"(r[1]), "=r"(r[2]), "=r"(r[3]) : "r"(addr));
}
__device__ __forceinline__ void mma_fp16(float* c, const uint32_t* a,
                                         uint32_t b0, uint32_t b1) {
    asm volatile(
        "mma.sync.aligned.m16n8k16.row.col.f32.f16.f16.f32 "
        "{%0,%1,%2,%3}, {%4,%5,%6,%7}, {%8,%9}, {%0,%1,%2,%3};"
        : "+f"(c[0]), "+f"(c[1]), "+f"(c[2]), "+f"(c[3])
        : "r"(a[0]), "r"(a[1]), "r"(a[2]), "r"(a[3]), "r"(b0), "r"(b1));
}

// ---------------------------------------------------------------------------
// Compaction A: per-b valid counts (grant-at-least-one). grid BB x 256.
// ---------------------------------------------------------------------------
__global__ void maskcnt_kernel(const unsigned* __restrict__ mask,
                               int* __restrict__ cnt) {
    const int b = blockIdx.x, n = threadIdx.x;
    const int raw = mask[(size_t)b * NN + n] != 0u;
    const int any = __syncthreads_or(raw);
    const int v = raw | ((!any) & (n == 0));
    const unsigned bal = __ballot_sync(0xFFFFFFFFu, v);
    __shared__ int wc[8];
    if ((n & 31) == 0) wc[n >> 5] = __popc(bal);
    __syncthreads();
    if (n == 0) {
        int s = 0;
        #pragma unroll
        for (int i = 0; i < 8; i++) s += wc[i];
        cnt[b] = s;
    }
}

// ---------------------------------------------------------------------------
// Compaction B: write fwd/inv maps + ntot (scan of counts done in-block).
// grid BB x 256.
// ---------------------------------------------------------------------------
__global__ void cwrite_kernel(const unsigned* __restrict__ mask,
                              const int* __restrict__ cnt,
                              int* __restrict__ fwd, int* __restrict__ inv,
                              int* __restrict__ ntot) {
    const int b = blockIdx.x, n = threadIdx.x;
    __shared__ int scnt[BB];
    __shared__ int s_off;
    __shared__ int wc[8];

    if (n < BB) scnt[n] = cnt[n];

    const int raw = mask[(size_t)b * NN + n] != 0u;
    const int any = __syncthreads_or(raw);   // barrier: scnt loads done
    const int v = raw | ((!any) & (n == 0));
    const unsigned bal = __ballot_sync(0xFFFFFFFFu, v);
    if ((n & 31) == 0) wc[n >> 5] = __popc(bal);
    if (n == 0) {
        int o = 0, tot = 0;
        #pragma unroll 4
        for (int i = 0; i < BB; i++) {
            if (i < b) o += scnt[i];
            tot += scnt[i];
        }
        s_off = o;
        if (b == 0) {
            ntot[0] = tot;
            ntot[1] = (tot + 127) & ~127;
        }
    }
    __syncthreads();

    int wbase = 0;
    for (int i = 0; i < (n >> 5); i++) wbase += wc[i];
    const int rank = s_off + wbase + __popc(bal & ((1u << (n & 31)) - 1u));
    if (v) {
        fwd[rank] = b * NN + n;
        inv[b * NN + n] = rank;
    } else {
        inv[b * NN + n] = -1;
    }
}

// ---------------------------------------------------------------------------
// Fused prep, 256 threads/block.
// Blocks [0, 48): weight prep, block -> (layer l, k-slab of 64, n-half).
//   Per-thread: 64 W loads (same per-thread work as the fast R15 shape).
// Blocks [48, 48+MROWS/2): 2 compact rows per block (128 threads/row):
//   gather via fwd, fp16 convert, mean/rstd. Early exit past padded count.
// ---------------------------------------------------------------------------
__global__ __launch_bounds__(256)
void prep_kernel(const float* __restrict__ Obs,
                 const int* __restrict__ fwd, const int* __restrict__ ntot,
                 __half* __restrict__ x16,
                 float* __restrict__ mean, float* __restrict__ rstd,
                 const float* __restrict__ W1, const float* __restrict__ W2,
                 const float* __restrict__ W3,
                 const float* __restrict__ g1, const float* __restrict__ g2,
                 const float* __restrict__ g3,
                 const float* __restrict__ b1, const float* __restrict__ b2,
                 const float* __restrict__ b3,
                 __half* __restrict__ wg,
                 float* __restrict__ Sp, float* __restrict__ Tp) {
    const int bid = blockIdx.x;
    const int tid = threadIdx.x;

    if (bid < 48) {
        // ---- weight prep: (l, slab, nh) ----
        const int l    = bid >> 4;         // 0..2
        const int rem  = bid & 15;
        const int slab = rem >> 1;          // 0..7
        const int nh   = rem & 1;           // 0..1
        const float* W = (l == 0) ? W1 : (l == 1) ? W2 : W3;
        const float* g = (l == 0) ? g1 : (l == 1) ? g2 : g3;
        const float* b = (l == 0) ? b1 : (l == 1) ? b2 : b3;
        __half* wgo = wg + (size_t)l * DD * OO;
        const int k0 = slab * 64;
        const int n  = nh * 256 + tid;

        __shared__ float sg[64], sb[64];
        if (tid < 64)            sg[tid] = g[k0 + tid];
        else if (tid < 128)      sb[tid - 64] = b[k0 + tid - 64];
        __syncthreads();

        float s = 0.f, t = 0.f;
        #pragma unroll
        for (int i8 = 0; i8 < 8; i8++) {
            __align__(16) __half h[8];
            #pragma unroll
            for (int j = 0; j < 8; j++) {
                const int kk = i8 * 8 + j;
                const float w = W[(size_t)(k0 + kk) * OO + n];
                const float gw = sg[kk] * w;
                s += gw;
                t += sb[kk] * w;
                h[j] = __float2half_rn(gw);
            }
            *reinterpret_cast<uint4*>(wgo + (size_t)n * DD + k0 + i8 * 8) =
                *reinterpret_cast<const uint4*>(h);
        }
        Sp[(size_t)(l * 8 + slab) * OO + n] = s;
        Tp[(size_t)(l * 8 + slab) * OO + n] = t;
    } else {
        // ---- 2 compact rows per block ----
        const int rbase = (bid - 48) * 2;
        if (rbase >= __ldg(&ntot[1])) return;   // padded %128 -> uniform
        const int total = __ldg(&ntot[0]);
        const int row = rbase + (tid >> 7);
        const int t = tid & 127;

        float4 v = make_float4(0.f, 0.f, 0.f, 0.f);
        if (row < total) {
            const int orig = __ldg(&fwd[row]);
            v = reinterpret_cast<const float4*>(Obs + (size_t)orig * DD)[t];
        }
        __half2* p = reinterpret_cast<__half2*>(x16 + (size_t)row * DD);
        p[t * 2]     = __halves2half2(__float2half_rn(v.x), __float2half_rn(v.y));
        p[t * 2 + 1] = __halves2half2(__float2half_rn(v.z), __float2half_rn(v.w));

        float s  = v.x + v.y + v.z + v.w;
        float ss = v.x * v.x + v.y * v.y + v.z * v.z + v.w * v.w;
        #pragma unroll
        for (int o = 16; o > 0; o >>= 1) {
            s  += __shfl_xor_sync(0xFFFFFFFFu, s,  o);
            ss += __shfl_xor_sync(0xFFFFFFFFu, ss, o);
        }
        __shared__ float sh_s[8], sh_ss[8];
        const int w = tid >> 5;
        if ((tid & 31) == 0) { sh_s[w] = s; sh_ss[w] = ss; }
        __syncthreads();
        if (t == 0) {
            const int wb = (tid >> 7) * 4;
            s  = sh_s[wb] + sh_s[wb + 1] + sh_s[wb + 2] + sh_s[wb + 3];
            ss = sh_ss[wb] + sh_ss[wb + 1] + sh_ss[wb + 2] + sh_ss[wb + 3];
            const float mn  = s * (1.0f / DD);
            const float var = ss * (1.0f / DD) - mn * mn;
            mean[row] = mn;
            rstd[row] = rsqrtf(var + 1e-5f);
        }
    }
}

// ---------------------------------------------------------------------------
// fp16 HMMA GEMM (compact rows) with fused LN affine epilogue.
// Prologue (hidden under mainloop): reduce per-column S/T from 8 slab
// partials; PSTATS: reduce per-row mean/rstd from 8 chunk partials.
// Blocks with m0 >= padded row count exit immediately.
// ---------------------------------------------------------------------------
template <bool TANH, bool STATS, bool RESID, bool PSTATS, typename OutT>
__global__ __launch_bounds__(256, 2)
void gemm_ln_kernel(const __half* __restrict__ A,
                    const __half* __restrict__ B,
                    const float* __restrict__ mean,
                    const float* __restrict__ rstd,
                    const float* __restrict__ psin,
                    const float* __restrict__ pqin,
                    const float* __restrict__ SpL,
                    const float* __restrict__ TpL,
                    const __half* __restrict__ resid,
                    float* __restrict__ ps,
                    float* __restrict__ pq,
                    OutT* __restrict__ C,
                    const int* __restrict__ ntot) {
    if ((int)(blockIdx.y * 128) >= __ldg(&ntot[1])) return;

    extern __shared__ char smem[];
    const uint32_t sb = smem_to_u32(smem);
    __shared__ float s_mn[128], s_rs[128];
    __shared__ float s_S[128], s_T[128];

    const int tid  = threadIdx.x;
    const int lane = tid & 31;
    const int wid  = tid >> 5;
    const int m0 = blockIdx.y * 128;
    const int n0 = blockIdx.x * 128;
    const int warp_m = (wid >> 1) * 32;
    const int warp_n = (wid & 1) * 64;

    // Prologues: latency hidden under the mainloop (ordered by its barriers)
    if (tid < 128) {
        float s = 0.f, t = 0.f;
        #pragma unroll
        for (int i = 0; i < 8; i++) {
            s += SpL[(size_t)i * OO + n0 + tid];
            t += TpL[(size_t)i * OO + n0 + tid];
        }
        s_S[tid] = s;
        s_T[tid] = t;
    } else if (PSTATS && tid < 256) {
        const int r = tid - 128;
        float s = 0.f, q = 0.f;
        #pragma unroll
        for (int i = 0; i < 8; i++) {
            s += psin[(size_t)(m0 + r) * 8 + i];
            q += pqin[(size_t)(m0 + r) * 8 + i];
        }
        const float mn  = s * (1.0f / DD);
        const float var = q * (1.0f / DD) - mn * mn;
        s_mn[r] = mn;
        s_rs[r] = rsqrtf(var + 1e-5f);
    }

    float acc[2][8][4];
    #pragma unroll
    for (int i = 0; i < 2; i++)
        #pragma unroll
        for (int j = 0; j < 8; j++)
            #pragma unroll
            for (int q = 0; q < 4; q++) acc[i][j][q] = 0.0f;

    const int arow  = warp_m + (lane & 7) + ((lane >> 3) & 1) * 8;
    const int akblk = (lane >> 4) & 1;
    const int ax    = arow & 3;
    const int brow  = warp_n + (lane & 7) + ((lane >> 4) & 1) * 8;
    const int bkblk = (lane >> 3) & 1;
    const int bx    = brow & 3;

    #define AOFF(mt, kb) \
        (uint32_t)((arow + (mt) * 16) * 64 + (((((kb) >> 3) + akblk) ^ ax) & 3) * 16)
    #define BOFF(jj, kb) \
        (uint32_t)((brow + (jj) * 16) * 64 + (((((kb) >> 3) + bkblk) ^ bx) & 3) * 16)

    const int c0row = tid >> 2,          c0ch = tid & 3;
    const int c1row = (tid + 256) >> 2;
    const uint32_t d0 = (uint32_t)(c0row * 64 + ((c0ch ^ (c0row & 3)) << 4));
    const uint32_t d1 = (uint32_t)(c1row * 64 + ((c0ch ^ (c1row & 3)) << 4));
    const size_t gA0 = (size_t)(m0 + c0row) * DD + c0ch * 8;
    const size_t gA1 = (size_t)(m0 + c1row) * DD + c0ch * 8;
    const size_t gB0 = (size_t)(n0 + c0row) * DD + c0ch * 8;
    const size_t gB1 = (size_t)(n0 + c1row) * DD + c0ch * 8;

    #define LOAD_STAGE(it, st) do {                                      \
        const int _k0 = (it) * 32;                                       \
        const uint32_t _sa = sb + (uint32_t)(st) * 16384u;               \
        const uint32_t _sbb = _sa + 8192u;                               \
        cp16(_sa + d0, A + gA0 + _k0);                                   \
        cp16(_sa + d1, A + gA1 + _k0);                                   \
        cp16(_sbb + d0, B + gB0 + _k0);                                  \
        cp16(_sbb + d1, B + gB1 + _k0);                                  \
        asm volatile("cp.async.commit_group;" ::: "memory");             \
    } while (0)

    LOAD_STAGE(0, 0);
    LOAD_STAGE(1, 1);

    const int NK = DD / 32;   // 16
    int st = 0;
    for (int it = 0; it < NK; it++) {
        if (it + 1 < NK) {
            asm volatile("cp.async.wait_group 1;" ::: "memory");
        } else {
            asm volatile("cp.async.wait_group 0;" ::: "memory");
        }
        __syncthreads();

        if (it + 2 < NK) {
            int st2 = st + 2; if (st2 >= 3) st2 -= 3;
            LOAD_STAGE(it + 2, st2);
        }

        const uint32_t sa  = sb + (uint32_t)st * 16384u;
        const uint32_t sbB = sa + 8192u;
        #pragma unroll
        for (int ks = 0; ks < 2; ks++) {
            const int kb = ks * 16;
            uint32_t af[2][4];
            #pragma unroll
            for (int mt = 0; mt < 2; mt++)
                ldm_x4(af[mt], sa + AOFF(mt, kb));
            uint32_t bf[4][4];
            #pragma unroll
            for (int jj = 0; jj < 4; jj++)
                ldm_x4(bf[jj], sbB + BOFF(jj, kb));
            #pragma unroll
            for (int j = 0; j < 8; j++) {
                const int jj = j >> 1, jh = (j & 1) * 2;
                const uint32_t b0 = bf[jj][jh], b1 = bf[jj][jh + 1];
                #pragma unroll
                for (int mt = 0; mt < 2; mt++)
                    mma_fp16(acc[mt][j], af[mt], b0, b1);
            }
        }
        if (++st >= 3) st = 0;
    }
    #undef LOAD_STAGE
    #undef AOFF
    #undef BOFF

    // Epilogue: fused LN affine (+tanh) (+residual) (+stats partials)
    #pragma unroll
    for (int mt = 0; mt < 2; mt++) {
        const int lr0 = warp_m + mt * 16 + (lane >> 2);
        const int lr1 = lr0 + 8;
        const int r0 = m0 + lr0, r1 = m0 + lr1;
        const float mn0 = PSTATS ? s_mn[lr0] : mean[r0];
        const float rs0 = PSTATS ? s_rs[lr0] : rstd[r0];
        const float mn1 = PSTATS ? s_mn[lr1] : mean[r1];
        const float rs1 = PSTATS ? s_rs[lr1] : rstd[r1];
        float s0 = 0.f, q0 = 0.f, s1 = 0.f, q1 = 0.f;
        #pragma unroll
        for (int j = 0; j < 8; j++) {
            const int cl = warp_n + j * 8 + (lane & 3) * 2;   // local column
            const int col = n0 + cl;
            const float sc0 = s_S[cl], sc1 = s_S[cl + 1];
            const float tc0 = s_T[cl], tc1 = s_T[cl + 1];
            float v0 = rs0 * (acc[mt][j][0] - mn0 * sc0) + tc0;
            float v1 = rs0 * (acc[mt][j][1] - mn0 * sc1) + tc1;
            float v2 = rs1 * (acc[mt][j][2] - mn1 * sc0) + tc0;
            float v3 = rs1 * (acc[mt][j][3] - mn1 * sc1) + tc1;
            if (TANH) { v0 = tanhf(v0); v1 = tanhf(v1); v2 = tanhf(v2); v3 = tanhf(v3); }
            if (RESID) {
                const __half2 h2a = *reinterpret_cast<const __half2*>(
                    resid + (size_t)r0 * OO + col);
                const __half2 h2b = *reinterpret_cast<const __half2*>(
                    resid + (size_t)r1 * OO + col);
                v0 += __half2float(__low2half(h2a));
                v1 += __half2float(__high2half(h2a));
                v2 += __half2float(__low2half(h2b));
                v3 += __half2float(__high2half(h2b));
            }
            if (sizeof(OutT) == 2) {
                const __half h0 = __float2half_rn(v0), h1 = __float2half_rn(v1);
                const __half h2 = __float2half_rn(v2), h3 = __float2half_rn(v3);
                *reinterpret_cast<__half2*>((__half*)C + (size_t)r0 * OO + col) =
                    __halves2half2(h0, h1);
                *reinterpret_cast<__half2*>((__half*)C + (size_t)r1 * OO + col) =
                    __halves2half2(h2, h3);
                if (STATS) {
                    const float f0 = __half2float(h0), f1 = __half2float(h1);
                    const float f2 = __half2float(h2), f3 = __half2float(h3);
                    s0 += f0 + f1; q0 += f0 * f0 + f1 * f1;
                    s1 += f2 + f3; q1 += f2 * f2 + f3 * f3;
                }
            } else {
                *reinterpret_cast<float2*>((float*)C + (size_t)r0 * OO + col) =
                    make_float2(v0, v1);
                *reinterpret_cast<float2*>((float*)C + (size_t)r1 * OO + col) =
                    make_float2(v2, v3);
            }
        }
        if (STATS) {
            #pragma unroll
            for (int o = 1; o <= 2; o <<= 1) {
                s0 += __shfl_xor_sync(0xFFFFFFFFu, s0, o);
                q0 += __shfl_xor_sync(0xFFFFFFFFu, q0, o);
                s1 += __shfl_xor_sync(0xFFFFFFFFu, s1, o);
                q1 += __shfl_xor_sync(0xFFFFFFFFu, q1, o);
            }
            if ((lane & 3) == 0) {
                const int chunk = blockIdx.x * 2 + (wid & 1);
                ps[(size_t)r0 * 8 + chunk] = s0;
                pq[(size_t)r0 * 8 + chunk] = q0;
                ps[(size_t)r1 * 8 + chunk] = s1;
                pq[(size_t)r1 * 8 + chunk] = q1;
            }
        }
    }
}

// ---------------------------------------------------------------------------
// Masked softmax over axis=1 with compact-row gather.
// grid (BB, 8), 256 threads; 256n x 64o panel staged in 64KB dynamic SMEM.
// ---------------------------------------------------------------------------
__global__ __launch_bounds__(256)
void softmax_kernel(float* __restrict__ out,
                    const float* __restrict__ o3c,
                    const int* __restrict__ inv) {
    extern __shared__ float sv[];   // [256][64]
    __shared__ int sidx[NN];
    __shared__ float red_m[4][64], red_s[4][64];

    const int b  = blockIdx.x;
    const int o0 = blockIdx.y * 64;
    const int tid = threadIdx.x;

    sidx[tid] = inv[b * NN + tid];
    __syncthreads();

    for (int idx = tid; idx < NN * 64; idx += 256) {
        const int n = idx >> 6, c = idx & 63;
        const int ci = sidx[n];
        sv[idx] = (ci >= 0) ? o3c[(size_t)ci * OO + o0 + c] : 0.0f;
    }
    __syncthreads();

    const int col = tid & 63;
    const int seg = tid >> 6;
    float m = -INFINITY, s = 0.0f;
    for (int n = seg * 64; n < seg * 64 + 64; n++) {
        if (sidx[n] >= 0) {
            const float v = sv[n * 64 + col];
            const float nm = fmaxf(m, v);
            s = s * __expf(m - nm) + __expf(v - nm);
            m = nm;
        }
    }
    red_m[seg][col] = m;
    red_s[seg][col] = s;
    __syncthreads();

    if (seg == 0) {
        float M = red_m[0][col];
        #pragma unroll
        for (int i = 1; i < 4; i++) M = fmaxf(M, red_m[i][col]);
        float SS = 0.0f;
        #pragma unroll
        for (int i = 0; i < 4; i++) {
            const float mi = red_m[i][col];
            if (mi != -INFINITY) SS += red_s[i][col] * __expf(mi - M);
        }
        red_m[0][col] = M;
        red_s[0][col] = 1.0f / SS;
    }
    __syncthreads();

    const float M  = red_m[0][col];
    const float rs = red_s[0][col];
    float* base = out + (size_t)b * NN * OO + o0;
    for (int n = seg * 64; n < seg * 64 + 64; n++) {
        const float v = (sidx[n] >= 0) ? __expf(sv[n * 64 + col] - M) * rs : 0.0f;
        base[(size_t)n * OO + col] = v;
    }
}

// ---------------------------------------------------------------------------
// Launch
// ---------------------------------------------------------------------------
extern "C" void kernel_launch(void* const* d_in, const int* in_sizes, int n_in,
                              void* d_out, int out_size) {
    const float*    Obs  = (const float*)d_in[0];
    const unsigned* mask = (const unsigned*)d_in[1];
    const float* g1 = (const float*)d_in[2];
    const float* b1 = (const float*)d_in[3];
    const float* W1 = (const float*)d_in[4];
    const float* g2 = (const float*)d_in[5];
    const float* b2 = (const float*)d_in[6];
    const float* W2 = (const float*)d_in[7];
    const float* g3 = (const float*)d_in[8];
    const float* b3 = (const float*)d_in[9];
    const float* W3 = (const float*)d_in[10];
    float* out = (float*)d_out;

    __half *x16, *h1, *wg;
    float *o3, *mean, *rstd, *Sp, *Tp, *ps1, *pq1, *ps2, *pq2;
    int *cnt, *ntot, *fwd, *inv;
    cudaGetSymbolAddress((void**)&x16, g_x16);
    cudaGetSymbolAddress((void**)&h1, g_h1);
    cudaGetSymbolAddress((void**)&o3, g_o3);
    cudaGetSymbolAddress((void**)&wg, g_wg);
    cudaGetSymbolAddress((void**)&mean, g_mean);
    cudaGetSymbolAddress((void**)&rstd, g_rstd);
    cudaGetSymbolAddress((void**)&Sp, g_Sp);
    cudaGetSymbolAddress((void**)&Tp, g_Tp);
    cudaGetSymbolAddress((void**)&ps1, g_ps1);
    cudaGetSymbolAddress((void**)&pq1, g_pq1);
    cudaGetSymbolAddress((void**)&ps2, g_ps2);
    cudaGetSymbolAddress((void**)&pq2, g_pq2);
    cudaGetSymbolAddress((void**)&cnt, g_cnt);
    cudaGetSymbolAddress((void**)&ntot, g_ntot);
    cudaGetSymbolAddress((void**)&fwd, g_fwd);
    cudaGetSymbolAddress((void**)&inv, g_inv);

    static bool attr_done = false;
    const int DSMEM = 49152;            // 3 stages x 16KB
    const int SMEM_SOFT = NN * 64 * 4;  // 64KB
    if (!attr_done) {
        cudaFuncSetAttribute(
            (const void*)gemm_ln_kernel<true, true, false, false, __half>,
            cudaFuncAttributeMaxDynamicSharedMemorySize, DSMEM);
        cudaFuncSetAttribute(
            (const void*)gemm_ln_kernel<true, true, true, true, __half>,
            cudaFuncAttributeMaxDynamicSharedMemorySize, DSMEM);
        cudaFuncSetAttribute(
            (const void*)gemm_ln_kernel<false, false, false, true, float>,
            cudaFuncAttributeMaxDynamicSharedMemorySize, DSMEM);
        cudaFuncSetAttribute((const void*)softmax_kernel,
                             cudaFuncAttributeMaxDynamicSharedMemorySize, SMEM_SOFT);
        attr_done = true;
    }

    const dim3 gGemm(OO / 128, MROWS / 128);   // (4, 256); tail blocks exit

    // Compaction (2 launches)
    maskcnt_kernel<<<BB, 256>>>(mask, cnt);
    cwrite_kernel<<<BB, 256>>>(mask, cnt, fwd, inv, ntot);

    // Fused prep: weight prep (48 blocks) + gather-stats rows (2/block)
    prep_kernel<<<48 + MROWS / 2, 256>>>(Obs, fwd, ntot, x16, mean, rstd,
                                         W1, W2, W3, g1, g2, g3, b1, b2, b3,
                                         wg, Sp, Tp);

    // Block 1: GEMM1 -> h1 (fp16 compact) + stats partials of h1
    gemm_ln_kernel<true, true, false, false, __half><<<gGemm, 256, DSMEM>>>(
        x16, wg, mean, rstd, nullptr, nullptr, Sp, Tp, nullptr,
        ps1, pq1, h1, ntot);

    // Block 2: GEMM2 -> x16 = fp16(h1 + tanh(...)) + stats partials
    gemm_ln_kernel<true, true, true, true, __half><<<gGemm, 256, DSMEM>>>(
        h1, wg + (size_t)DD * OO, nullptr, nullptr, ps1, pq1,
        Sp + 8 * OO, Tp + 8 * OO, h1, ps2, pq2, x16, ntot);

    // Block 3: GEMM3 -> o3 (fp32 compact)
    gemm_ln_kernel<false, false, false, true, float><<<gGemm, 256, DSMEM>>>(
        x16, wg + 2 * (size_t)DD * OO, nullptr, nullptr, ps2, pq2,
        Sp + 16 * OO, Tp + 16 * OO, nullptr, nullptr, nullptr, o3, ntot);

    // Masked softmax over axis=1: gather compact rows, write dense output
    softmax_kernel<<<dim3(BB, 8), 256, SMEM_SOFT>>>(out, o3, inv);
}